// round 8
// baseline (speedup 1.0000x reference)
#include <cuda_runtime.h>
#include <cuda_fp16.h>
#include <cstdint>
#include <cstddef>

#define NB 1024
#define NT 64
#define NF 121
#define NH 512
#define NSEG 32
#define NG 2048   // 4*H

// ---------------- scratch (device globals; no allocation) ----------------
__device__ __align__(16) float   g_Z   [(size_t)NB * NT * NG];    // precomputed z (interleaved cols)
__device__ __align__(16) __half  g_X   [(size_t)NB * NT * 128];   // x fp16, K padded 121->128
__device__ __align__(16) __half  g_Y   [(size_t)NB * NT * NH];    // y0 / d0 staging (fp16)
__device__ __align__(16) float   g_D1  [(size_t)NB * NSEG * NH];  // decoder L1 outputs
__device__ __align__(16) __half  g_hA  [2][NB * NH];              // ping-pong h (enc0->dec0)
__device__ __align__(16) __half  g_hB  [2][NB * NH];              // (enc1->dec1)
__device__ __align__(16) float   g_cA  [NB * NH];
__device__ __align__(16) float   g_cB  [NB * NH];
// weight arena: W^T fp16, rows = interleaved out-col (j*4+gate), K contiguous.
#define O_eW0 0
#define O_eU0 (2048*128)
#define O_eW1 (O_eU0 + 2048*512)
#define O_eU1 (O_eW1 + 2048*512)
#define O_dU0 (O_eU1 + 2048*512)
#define O_dW1 (O_dU0 + 2048*512)
#define O_dU1 (O_dW1 + 2048*512)
#define W_TOTAL (O_dU1 + 2048*512)
__device__ __align__(16) __half  g_WT  [W_TOTAL];
__device__ __align__(16) float   g_bias[4 * NG];   // eb0,eb1,db0,db1 (interleaved)

// ---------------- helpers ----------------
__device__ __forceinline__ float rcpa(float x) {
    float r; asm("rcp.approx.f32 %0, %1;" : "=f"(r) : "f"(x)); return r;
}
__device__ __forceinline__ float sigf(float x)  { return rcpa(1.0f + __expf(-x)); }
__device__ __forceinline__ float tanhff(float x){ return __fmaf_rn(2.0f, rcpa(1.0f + __expf(-2.0f * x)), -1.0f); }

__device__ __forceinline__ uint32_t smem_u32(const void* p) {
    uint32_t a;
    asm("{ .reg .u64 t; cvta.to.shared.u64 t, %1; cvt.u32.u64 %0, t; }" : "=r"(a) : "l"(p));
    return a;
}
__device__ __forceinline__ void mma16816h(float* d, const unsigned* a, unsigned b0, unsigned b1) {
    asm volatile(
        "mma.sync.aligned.m16n8k16.row.col.f32.f16.f16.f32 "
        "{%0,%1,%2,%3}, {%4,%5,%6,%7}, {%8,%9}, {%0,%1,%2,%3};"
        : "+f"(d[0]), "+f"(d[1]), "+f"(d[2]), "+f"(d[3])
        : "r"(a[0]), "r"(a[1]), "r"(a[2]), "r"(a[3]), "r"(b0), "r"(b1));
}
__device__ __forceinline__ void ldsm4(uint32_t* r, uint32_t addr) {
    asm volatile("ldmatrix.sync.aligned.m8n8.x4.shared.b16 {%0,%1,%2,%3}, [%4];"
                 : "=r"(r[0]), "=r"(r[1]), "=r"(r[2]), "=r"(r[3]) : "r"(addr));
}
__device__ __forceinline__ void cpa16(uint32_t dst, const void* src) {
    asm volatile("cp.async.cg.shared.global [%0], [%1], 16;" :: "r"(dst), "l"(src));
}
#define CP_COMMIT() asm volatile("cp.async.commit_group;" ::: "memory")

// smem: three 40KB stages: A 8K | B 32K
#define BUF_STRIDE 40960u
#define SMEM_DYN   (3 * 40960)

// ---------------- merged prep kernels ----------------
__global__ void k_prep_weights(const float* __restrict__ eW0, const float* __restrict__ eU0,
                               const float* __restrict__ eW1, const float* __restrict__ eU1,
                               const float* __restrict__ dU0, const float* __restrict__ dW1,
                               const float* __restrict__ dU1) {
    long long idx = (long long)blockIdx.x * blockDim.x + threadIdx.x;
    const float* src; int K, Kpad; size_t off;
    const long long S0 = 2048LL * 128, S = 2048LL * 512;
    if (idx < S0)               { src = eW0; K = NF;  Kpad = 128; off = O_eW0; }
    else if ((idx -= S0) < S)   { src = eU0; K = NH;  Kpad = 512; off = O_eU0; }
    else if ((idx -= S) < S)    { src = eW1; K = NH;  Kpad = 512; off = O_eW1; }
    else if ((idx -= S) < S)    { src = eU1; K = NH;  Kpad = 512; off = O_eU1; }
    else if ((idx -= S) < S)    { src = dU0; K = NH;  Kpad = 512; off = O_dU0; }
    else if ((idx -= S) < S)    { src = dW1; K = NH;  Kpad = 512; off = O_dW1; }
    else if ((idx -= S) < S)    { src = dU1; K = NH;  Kpad = 512; off = O_dU1; }
    else return;
    int n = (int)(idx / Kpad), k = (int)(idx % Kpad);
    float v = (k < K) ? src[(size_t)k * NG + n] : 0.0f;
    int cil = (n & 511) * 4 + (n >> 9);
    g_WT[off + (size_t)cil * Kpad + k] = __float2half(v);
}

__global__ void k_prep_misc(const float* __restrict__ x,
                            const float* __restrict__ eb0, const float* __restrict__ eb1,
                            const float* __restrict__ db0, const float* __restrict__ db1) {
    long long idx = (long long)blockIdx.x * blockDim.x + threadIdx.x;
    if (idx < 4 * NG) {
        int which = (int)(idx >> 11), n = (int)(idx & 2047);
        const float* b = (which == 0) ? eb0 : (which == 1) ? eb1 : (which == 2) ? db0 : db1;
        g_bias[which * NG + (n & 511) * 4 + (n >> 9)] = b[n];
        return;
    }
    idx -= 4 * NG;
    if (idx < (long long)NB * NT * 128) {
        int r = (int)(idx >> 7), k = (int)(idx & 127);
        g_X[idx] = __float2half((k < NF) ? x[(size_t)r * NF + k] : 0.0f);
        return;
    }
    idx -= (long long)NB * NT * 128;
    if (idx < NB * NH) {
        __half z = __float2half(0.0f);
        g_hA[0][idx] = z; g_hB[0][idx] = z;
        g_cA[idx] = 0.0f; g_cB[idx] = 0.0f;
    }
}

// ---------------- fp16 GEMM, 512 threads, 3-stage cp.async pipeline ----------------
// C[M][2048] = A[M][K] @ B^T ; A fp16, B stored [n][k] K-contig fp16.
// Tile BM=64 x BN=256; 16 warps (2x8), warp tile 32x32. K chunks of 64, 3 smem stages.
template <bool LSTM>
__global__ __launch_bounds__(512)
void k_gemm1(const __half* __restrict__ A, int lda,
             const __half* __restrict__ B, int ldw,
             int nc,
             float* __restrict__ outZ,
             const float* __restrict__ pre, long long preStride,
             const float* __restrict__ bias,
             float* __restrict__ cState,
             __half* __restrict__ hOut,
             __half* __restrict__ yOut, long long yStride,
             float* __restrict__ yF32) {
    extern __shared__ __align__(128) char smem[];
    const uint32_t sb = smem_u32(smem);
    const int tid = threadIdx.x, lane = tid & 31, warp = tid >> 5;
    const int wm = warp >> 3;          // 0..1  (32 M-rows each)
    const int wn = warp & 7;           // 0..7  (32 N-cols each)
    const int bm = blockIdx.x * 64;
    const int bn = blockIdx.y * 256;

    float acc[2][4][4];
#pragma unroll
    for (int a = 0; a < 2; a++)
#pragma unroll
        for (int b = 0; b < 4; b++)
#pragma unroll
            for (int c = 0; c < 4; c++) acc[a][b][c] = 0.0f;

    const uint32_t a_lc = (uint32_t)(lane & 16);            // ldmatrix col sel
    const uint32_t b_lc = (uint32_t)((lane & 8) << 1);
    const int b_r8 = (lane & 16) >> 1;

    auto issue = [&](int c) {
        const int kb = c * 64;
        const uint32_t dbase = sb + (uint32_t)(c % 3) * BUF_STRIDE;
        {   // A: 64 rows x 128B = 512 x 16B, one per thread
            int row = tid >> 3, seg = tid & 7;
            uint32_t off = (uint32_t)(row * 128) + (uint32_t)((seg * 16) ^ ((row & 7) * 16));
            cpa16(dbase + off, A + (size_t)(bm + row) * lda + kb + seg * 8);
        }
        {   // B: 256 rows x 128B = 2048 x 16B, four per thread
            const uint32_t db = dbase + 8192u;
#pragma unroll
            for (int it = 0; it < 4; it++) {
                int u = it * 512 + tid;
                int row = u >> 3, seg = u & 7;
                uint32_t off = (uint32_t)(row * 128) + (uint32_t)((seg * 16) ^ ((row & 7) * 16));
                cpa16(db + off, B + (size_t)(bn + row) * ldw + kb + seg * 8);
            }
        }
        CP_COMMIT();
    };

    issue(0);
    if (nc > 1) issue(1);
    for (int c = 0; c < nc; ++c) {
        if (c + 1 < nc) {
            asm volatile("cp.async.wait_group 1;" ::: "memory");
        } else {
            asm volatile("cp.async.wait_group 0;" ::: "memory");
        }
        __syncthreads();                 // single barrier per chunk
        if (c + 2 < nc) issue(c + 2);    // into the stage freed by chunk c-1
        const uint32_t dbase = sb + (uint32_t)(c % 3) * BUF_STRIDE;
#pragma unroll
        for (int k16 = 0; k16 < 4; ++k16) {
            const uint32_t kcol = (uint32_t)(k16 * 32);
            uint32_t af[2][4];
#pragma unroll
            for (int mt = 0; mt < 2; ++mt) {
                int r = wm * 32 + mt * 16 + (lane & 15);
                uint32_t addr = dbase + (uint32_t)(r * 128)
                              + ((kcol + a_lc) ^ (uint32_t)((r & 7) * 16));
                ldsm4(af[mt], addr);
            }
            uint32_t bfr[4][2];
#pragma unroll
            for (int jq = 0; jq < 2; ++jq) {
                int r = wn * 32 + jq * 16 + (lane & 7) + b_r8;
                uint32_t addr = dbase + 8192u + (uint32_t)(r * 128)
                              + ((kcol + b_lc) ^ (uint32_t)((r & 7) * 16));
                uint32_t t4[4];
                ldsm4(t4, addr);
                bfr[jq * 2][0] = t4[0];     bfr[jq * 2][1] = t4[1];
                bfr[jq * 2 + 1][0] = t4[2]; bfr[jq * 2 + 1][1] = t4[3];
            }
#pragma unroll
            for (int jt = 0; jt < 4; ++jt)
#pragma unroll
                for (int mt = 0; mt < 2; ++mt)
                    mma16816h(acc[mt][jt], af[mt], bfr[jt][0], bfr[jt][1]);
        }
    }

    // ---------------- epilogue ----------------
    if (!LSTM) {
#pragma unroll
        for (int mt = 0; mt < 2; mt++) {
            int r = bm + wm * 32 + mt * 16 + (lane >> 2);
#pragma unroll
            for (int jt = 0; jt < 4; jt++) {
                int cix = bn + wn * 32 + jt * 8 + (lane & 3) * 2;
                float* o = outZ + (size_t)r * NG + cix;
                o[0] = acc[mt][jt][0]; o[1] = acc[mt][jt][1];
                o += (size_t)8 * NG;
                o[0] = acc[mt][jt][2]; o[1] = acc[mt][jt][3];
            }
        }
    } else {
        // all-lane LSTM epilogue: even lane -> row rA, odd lane -> rA+8.
        const int par = lane & 1;
#pragma unroll
        for (int mt = 0; mt < 2; mt++) {
            const int rA = bm + wm * 32 + mt * 16 + (lane >> 2);
            const int r  = rA + par * 8;
#pragma unroll
            for (int jt = 0; jt < 4; jt++) {
                const int cix = bn + wn * 32 + jt * 8 + (lane & 3) * 2;
                float z0 = acc[mt][jt][0] + bias[cix];
                float z1 = acc[mt][jt][1] + bias[cix + 1];
                float z2 = acc[mt][jt][2] + bias[cix];
                float z3 = acc[mt][jt][3] + bias[cix + 1];
                if (pre) {
                    z0 += pre[(size_t)rA * preStride + cix];
                    z1 += pre[(size_t)rA * preStride + cix + 1];
                    z2 += pre[(size_t)(rA + 8) * preStride + cix];
                    z3 += pre[(size_t)(rA + 8) * preStride + cix + 1];
                }
                float s0 = par ? z0 : z2;
                float s1 = par ? z1 : z3;
                float q0 = __shfl_xor_sync(0xffffffffu, s0, 1);
                float q1 = __shfl_xor_sync(0xffffffffu, s1, 1);
                float zi = par ? q0 : z0;
                float zf = par ? q1 : z1;
                float zg = par ? z2 : q0;
                float zo = par ? z3 : q1;
                const int j = cix >> 2;
                const size_t si = (size_t)r * NH + j;
                float ig = sigf(zi), fg = sigf(zf), og = sigf(zo);
                float gg = tanhff(zg);
                float cn = fg * cState[si] + ig * gg;
                float h = og * tanhff(cn);
                cState[si] = cn;
                __half hh = __float2half(h);
                hOut[si] = hh;
                if (yOut) yOut[(size_t)r * yStride + j] = hh;
                if (yF32) yF32[(size_t)r * yStride + j] = h;
            }
        }
    }
}

// ---------------- final dense ----------------
__global__ void k_dense(const float* __restrict__ w, const float* __restrict__ b,
                        float* __restrict__ out) {
    int r = blockIdx.x * 8 + (threadIdx.x >> 5);
    int lane = threadIdx.x & 31;
    const float* row = g_D1 + (size_t)r * NH;
    float s = 0.0f;
#pragma unroll
    for (int k = lane; k < NH; k += 32) s += row[k] * w[k];
#pragma unroll
    for (int o = 16; o; o >>= 1) s += __shfl_xor_sync(0xffffffffu, s, o);
    if (lane == 0) out[r] = s + b[0];
}

// ---------------- host ----------------
extern "C" void kernel_launch(void* const* d_in, const int* in_sizes, int n_in,
                              void* d_out, int out_size) {
    (void)in_sizes; (void)n_in; (void)out_size;
    const float* x      = (const float*)d_in[0];
    const float* eW0    = (const float*)d_in[2];
    const float* eU0    = (const float*)d_in[3];
    const float* eb0    = (const float*)d_in[4];
    const float* eW1    = (const float*)d_in[5];
    const float* eU1    = (const float*)d_in[6];
    const float* eb1    = (const float*)d_in[7];
    const float* dU0    = (const float*)d_in[9];
    const float* db0    = (const float*)d_in[10];
    const float* dW1    = (const float*)d_in[11];
    const float* dU1    = (const float*)d_in[12];
    const float* db1    = (const float*)d_in[13];
    const float* denseW = (const float*)d_in[14];
    const float* denseb = (const float*)d_in[15];

    cudaFuncSetAttribute(k_gemm1<true>,  cudaFuncAttributeMaxDynamicSharedMemorySize, SMEM_DYN);
    cudaFuncSetAttribute(k_gemm1<false>, cudaFuncAttributeMaxDynamicSharedMemorySize, SMEM_DYN);

    void *pZ, *pX, *pY, *pD1, *pA, *pB, *pCA, *pCB, *pW, *pBs;
    cudaGetSymbolAddress(&pZ, g_Z);
    cudaGetSymbolAddress(&pX, g_X);
    cudaGetSymbolAddress(&pY, g_Y);
    cudaGetSymbolAddress(&pD1, g_D1);
    cudaGetSymbolAddress(&pA, g_hA);
    cudaGetSymbolAddress(&pB, g_hB);
    cudaGetSymbolAddress(&pCA, g_cA);  cudaGetSymbolAddress(&pCB, g_cB);
    cudaGetSymbolAddress(&pW, g_WT);
    cudaGetSymbolAddress(&pBs, g_bias);

    float* Z = (float*)pZ;
    __half* X = (__half*)pX;
    __half* Y = (__half*)pY;
    float* D1 = (float*)pD1;
    __half* hA[2] = {(__half*)pA, (__half*)pA + NB * NH};
    __half* hB[2] = {(__half*)pB, (__half*)pB + NB * NH};
    float* cA = (float*)pCA; float* cB = (float*)pCB;
    __half* W = (__half*)pW;
    float* Bias = (float*)pBs;

    // --- prep: 2 launches ---
    {
        long long wtot = 2048LL * 128 + 6LL * 2048 * 512;
        k_prep_weights<<<(int)((wtot + 255) / 256), 256>>>(eW0, eU0, eW1, eU1, dU0, dW1, dU1);
        long long mtot = 4LL * NG + (long long)NB * NT * 128 + (long long)NB * NH;
        k_prep_misc<<<(int)((mtot + 255) / 256), 256>>>(x, eb0, eb1, db0, db1);
    }

    const dim3 blk(512);
    const dim3 gStep(NB / 64, 8);   // 128 CTAs

    // --- encoder L0: precompute x@eW0, then 64 recurrent steps ---
    k_gemm1<false><<<dim3(NB * NT / 64, 8), blk, SMEM_DYN>>>(
        X, 128, W + O_eW0, 128, 2, Z,
        nullptr, 0, nullptr, nullptr, nullptr, nullptr, 0, nullptr);
    for (int t = 0; t < NT; t++) {
        k_gemm1<true><<<gStep, blk, SMEM_DYN>>>(
            hA[t & 1], NH, W + O_eU0, NH, 8, nullptr,
            Z + (size_t)t * NG, (long long)NT * NG, Bias + 0 * NG, cA,
            hA[(t + 1) & 1],
            Y + (size_t)t * NH, (long long)NT * NH, nullptr);
    }
    // --- encoder L1: precompute y0@eW1, then 64 steps ---
    k_gemm1<false><<<dim3(NB * NT / 64, 8), blk, SMEM_DYN>>>(
        Y, NH, W + O_eW1, NH, 8, Z,
        nullptr, 0, nullptr, nullptr, nullptr, nullptr, 0, nullptr);
    for (int t = 0; t < NT; t++) {
        k_gemm1<true><<<gStep, blk, SMEM_DYN>>>(
            hB[t & 1], NH, W + O_eU1, NH, 8, nullptr,
            Z + (size_t)t * NG, (long long)NT * NG, Bias + 1 * NG, cB,
            hB[(t + 1) & 1],
            nullptr, 0, nullptr);
    }
    // --- decoder L0: zero input; continues from enc-L0 final state ---
    for (int t = 0; t < NSEG; t++) {
        k_gemm1<true><<<gStep, blk, SMEM_DYN>>>(
            hA[t & 1], NH, W + O_dU0, NH, 8, nullptr,
            nullptr, 0, Bias + 2 * NG, cA,
            hA[(t + 1) & 1],
            Y + (size_t)t * NH, (long long)NSEG * NH, nullptr);
    }
    // --- decoder L1: precompute d0@dW1, then 32 steps, emit fp32 d1 ---
    k_gemm1<false><<<dim3(NB * NSEG / 64, 8), blk, SMEM_DYN>>>(
        Y, NH, W + O_dW1, NH, 8, Z,
        nullptr, 0, nullptr, nullptr, nullptr, nullptr, 0, nullptr);
    for (int t = 0; t < NSEG; t++) {
        k_gemm1<true><<<gStep, blk, SMEM_DYN>>>(
            hB[t & 1], NH, W + O_dU1, NH, 8, nullptr,
            Z + (size_t)t * NG, (long long)NSEG * NG, Bias + 3 * NG, cB,
            hB[(t + 1) & 1],
            nullptr, (long long)NSEG * NH, D1 + (size_t)t * NH);
    }
    // --- final dense ---
    k_dense<<<NB * NSEG / 8, 256>>>(denseW, denseb, (float*)d_out);
}

// round 10
// speedup vs baseline: 1.3641x; 1.3641x over previous
#include <cuda_runtime.h>
#include <cuda_fp16.h>
#include <cstdint>
#include <cstddef>

#define NB 1024
#define NT 64
#define NF 121
#define NH 512
#define NSEG 32
#define NG 2048   // 4*H

// ---------------- scratch (device globals; no allocation) ----------------
__device__ __align__(16) float   g_Z   [(size_t)NB * NT * NG];    // precomputed z (interleaved cols)
__device__ __align__(16) __half  g_X   [(size_t)NB * NT * 128];   // x fp16, K padded 121->128
__device__ __align__(16) __half  g_Y   [(size_t)NB * NT * NH];    // y0 / d0 staging (fp16)
__device__ __align__(16) float   g_D1  [(size_t)NB * NSEG * NH];  // decoder L1 outputs
__device__ __align__(16) __half  g_hA  [2][NB * NH];              // ping-pong h (enc0->dec0)
__device__ __align__(16) __half  g_hB  [2][NB * NH];              // (enc1->dec1)
__device__ __align__(16) float   g_cA  [NB * NH];
__device__ __align__(16) float   g_cB  [NB * NH];
// weight arena: W^T fp16, rows = interleaved out-col (j*4+gate), K contiguous.
#define O_eW0 0
#define O_eU0 (2048*128)
#define O_eW1 (O_eU0 + 2048*512)
#define O_eU1 (O_eW1 + 2048*512)
#define O_dU0 (O_eU1 + 2048*512)
#define O_dW1 (O_dU0 + 2048*512)
#define O_dU1 (O_dW1 + 2048*512)
#define W_TOTAL (O_dU1 + 2048*512)
__device__ __align__(16) __half  g_WT  [W_TOTAL];
__device__ __align__(16) float   g_bias[4 * NG];   // eb0,eb1,db0,db1 (interleaved)

// ---------------- helpers ----------------
__device__ __forceinline__ float rcpa(float x) {
    float r; asm("rcp.approx.f32 %0, %1;" : "=f"(r) : "f"(x)); return r;
}
__device__ __forceinline__ float sigf(float x)  { return rcpa(1.0f + __expf(-x)); }
__device__ __forceinline__ float tanhff(float x){ return __fmaf_rn(2.0f, rcpa(1.0f + __expf(-2.0f * x)), -1.0f); }

__device__ __forceinline__ uint32_t smem_u32(const void* p) {
    uint32_t a;
    asm("{ .reg .u64 t; cvta.to.shared.u64 t, %1; cvt.u32.u64 %0, t; }" : "=r"(a) : "l"(p));
    return a;
}
__device__ __forceinline__ void mma16816h(float* d, const unsigned* a, unsigned b0, unsigned b1) {
    asm volatile(
        "mma.sync.aligned.m16n8k16.row.col.f32.f16.f16.f32 "
        "{%0,%1,%2,%3}, {%4,%5,%6,%7}, {%8,%9}, {%0,%1,%2,%3};"
        : "+f"(d[0]), "+f"(d[1]), "+f"(d[2]), "+f"(d[3])
        : "r"(a[0]), "r"(a[1]), "r"(a[2]), "r"(a[3]), "r"(b0), "r"(b1));
}
__device__ __forceinline__ void ldsm4(uint32_t* r, uint32_t addr) {
    asm volatile("ldmatrix.sync.aligned.m8n8.x4.shared.b16 {%0,%1,%2,%3}, [%4];"
                 : "=r"(r[0]), "=r"(r[1]), "=r"(r[2]), "=r"(r[3]) : "r"(addr));
}
__device__ __forceinline__ void cpa16(uint32_t dst, const void* src) {
    asm volatile("cp.async.cg.shared.global [%0], [%1], 16;" :: "r"(dst), "l"(src));
}
#define CP_COMMIT() asm volatile("cp.async.commit_group;" ::: "memory")

// smem: three 20KB stages: A 4K | B 16K
#define BUF_STRIDE 20480u
#define SMEM_DYN   (3 * 20480)

// ---------------- merged prep kernels ----------------
__global__ void k_prep_weights(const float* __restrict__ eW0, const float* __restrict__ eU0,
                               const float* __restrict__ eW1, const float* __restrict__ eU1,
                               const float* __restrict__ dU0, const float* __restrict__ dW1,
                               const float* __restrict__ dU1) {
    long long idx = (long long)blockIdx.x * blockDim.x + threadIdx.x;
    const float* src; int K, Kpad; size_t off;
    const long long S0 = 2048LL * 128, S = 2048LL * 512;
    if (idx < S0)               { src = eW0; K = NF;  Kpad = 128; off = O_eW0; }
    else if ((idx -= S0) < S)   { src = eU0; K = NH;  Kpad = 512; off = O_eU0; }
    else if ((idx -= S) < S)    { src = eW1; K = NH;  Kpad = 512; off = O_eW1; }
    else if ((idx -= S) < S)    { src = eU1; K = NH;  Kpad = 512; off = O_eU1; }
    else if ((idx -= S) < S)    { src = dU0; K = NH;  Kpad = 512; off = O_dU0; }
    else if ((idx -= S) < S)    { src = dW1; K = NH;  Kpad = 512; off = O_dW1; }
    else if ((idx -= S) < S)    { src = dU1; K = NH;  Kpad = 512; off = O_dU1; }
    else return;
    int n = (int)(idx / Kpad), k = (int)(idx % Kpad);
    float v = (k < K) ? src[(size_t)k * NG + n] : 0.0f;
    int cil = (n & 511) * 4 + (n >> 9);
    g_WT[off + (size_t)cil * Kpad + k] = __float2half(v);
}

__global__ void k_prep_misc(const float* __restrict__ x,
                            const float* __restrict__ eb0, const float* __restrict__ eb1,
                            const float* __restrict__ db0, const float* __restrict__ db1) {
    long long idx = (long long)blockIdx.x * blockDim.x + threadIdx.x;
    if (idx < 4 * NG) {
        int which = (int)(idx >> 11), n = (int)(idx & 2047);
        const float* b = (which == 0) ? eb0 : (which == 1) ? eb1 : (which == 2) ? db0 : db1;
        g_bias[which * NG + (n & 511) * 4 + (n >> 9)] = b[n];
        return;
    }
    idx -= 4 * NG;
    if (idx < (long long)NB * NT * 128) {
        int r = (int)(idx >> 7), k = (int)(idx & 127);
        g_X[idx] = __float2half((k < NF) ? x[(size_t)r * NF + k] : 0.0f);
        return;
    }
    idx -= (long long)NB * NT * 128;
    if (idx < NB * NH) {
        __half z = __float2half(0.0f);
        g_hA[0][idx] = z; g_hB[0][idx] = z;
        g_cA[idx] = 0.0f; g_cB[idx] = 0.0f;
    }
}

// ---------------- fp16 GEMM: small CTAs, 3 CTAs/SM, 3-stage cp.async ----------------
// C[M][2048] = A[M][K] @ B^T ; A fp16, B stored [n][k] K-contig fp16.
// Tile BM=32 x BN=128; 8 warps (2x4), warp tile 16x32. K chunks of 64, 3 smem stages.
template <bool LSTM>
__global__ __launch_bounds__(256, 3)
void k_gemm1(const __half* __restrict__ A, int lda,
             const __half* __restrict__ B, int ldw,
             int nc,
             float* __restrict__ outZ,
             const float* __restrict__ pre, long long preStride,
             const float* __restrict__ bias,
             float* __restrict__ cState,
             __half* __restrict__ hOut,
             __half* __restrict__ yOut, long long yStride,
             float* __restrict__ yF32) {
    extern __shared__ __align__(128) char smem[];
    const uint32_t sb = smem_u32(smem);
    const int tid = threadIdx.x, lane = tid & 31, warp = tid >> 5;
    const int wm = warp >> 2;          // 0..1  (16 M-rows each)
    const int wn = warp & 3;           // 0..3  (32 N-cols each)
    const int bm = blockIdx.x * 32;
    const int bn = blockIdx.y * 128;

    float acc[4][4];
#pragma unroll
    for (int b = 0; b < 4; b++)
#pragma unroll
        for (int c = 0; c < 4; c++) acc[b][c] = 0.0f;

    const uint32_t a_lc = (uint32_t)(lane & 16);            // ldmatrix col sel
    const uint32_t b_lc = (uint32_t)((lane & 8) << 1);
    const int b_r8 = (lane & 16) >> 1;

    auto issue = [&](int c) {
        const int kb = c * 64;
        const uint32_t dbase = sb + (uint32_t)(c % 3) * BUF_STRIDE;
        {   // A: 32 rows x 128B = 256 x 16B, one per thread
            int row = tid >> 3, seg = tid & 7;
            uint32_t off = (uint32_t)(row * 128) + (uint32_t)((seg * 16) ^ ((row & 7) * 16));
            cpa16(dbase + off, A + (size_t)(bm + row) * lda + kb + seg * 8);
        }
        {   // B: 128 rows x 128B = 1024 x 16B, four per thread
            const uint32_t db = dbase + 4096u;
#pragma unroll
            for (int it = 0; it < 4; it++) {
                int u = it * 256 + tid;
                int row = u >> 3, seg = u & 7;
                uint32_t off = (uint32_t)(row * 128) + (uint32_t)((seg * 16) ^ ((row & 7) * 16));
                cpa16(db + off, B + (size_t)(bn + row) * ldw + kb + seg * 8);
            }
        }
        CP_COMMIT();
    };

    issue(0);
    if (nc > 1) issue(1);
    for (int c = 0; c < nc; ++c) {
        if (c + 1 < nc) {
            asm volatile("cp.async.wait_group 1;" ::: "memory");
        } else {
            asm volatile("cp.async.wait_group 0;" ::: "memory");
        }
        __syncthreads();                 // single barrier per chunk
        if (c + 2 < nc) issue(c + 2);    // into the stage freed by chunk c-1
        const uint32_t dbase = sb + (uint32_t)(c % 3) * BUF_STRIDE;
#pragma unroll
        for (int k16 = 0; k16 < 4; ++k16) {
            const uint32_t kcol = (uint32_t)(k16 * 32);
            uint32_t af[4];
            {
                int r = wm * 16 + (lane & 15);
                uint32_t addr = dbase + (uint32_t)(r * 128)
                              + ((kcol + a_lc) ^ (uint32_t)((r & 7) * 16));
                ldsm4(af, addr);
            }
            uint32_t bfr[4][2];
#pragma unroll
            for (int jq = 0; jq < 2; ++jq) {
                int r = wn * 32 + jq * 16 + (lane & 7) + b_r8;
                uint32_t addr = dbase + 4096u + (uint32_t)(r * 128)
                              + ((kcol + b_lc) ^ (uint32_t)((r & 7) * 16));
                uint32_t t4[4];
                ldsm4(t4, addr);
                bfr[jq * 2][0] = t4[0];     bfr[jq * 2][1] = t4[1];
                bfr[jq * 2 + 1][0] = t4[2]; bfr[jq * 2 + 1][1] = t4[3];
            }
#pragma unroll
            for (int jt = 0; jt < 4; ++jt)
                mma16816h(acc[jt], af, bfr[jt][0], bfr[jt][1]);
        }
    }

    // ---------------- epilogue ----------------
    if (!LSTM) {
        int r = bm + wm * 16 + (lane >> 2);
#pragma unroll
        for (int jt = 0; jt < 4; jt++) {
            int cix = bn + wn * 32 + jt * 8 + (lane & 3) * 2;
            float* o = outZ + (size_t)r * NG + cix;
            o[0] = acc[jt][0]; o[1] = acc[jt][1];
            o += (size_t)8 * NG;
            o[0] = acc[jt][2]; o[1] = acc[jt][3];
        }
    } else {
        // all-lane LSTM epilogue: even lane -> row rA, odd lane -> rA+8.
        const int par = lane & 1;
        const int rA = bm + wm * 16 + (lane >> 2);
        const int r  = rA + par * 8;
#pragma unroll
        for (int jt = 0; jt < 4; jt++) {
            const int cix = bn + wn * 32 + jt * 8 + (lane & 3) * 2;
            float z0 = acc[jt][0] + bias[cix];
            float z1 = acc[jt][1] + bias[cix + 1];
            float z2 = acc[jt][2] + bias[cix];
            float z3 = acc[jt][3] + bias[cix + 1];
            if (pre) {
                z0 += pre[(size_t)rA * preStride + cix];
                z1 += pre[(size_t)rA * preStride + cix + 1];
                z2 += pre[(size_t)(rA + 8) * preStride + cix];
                z3 += pre[(size_t)(rA + 8) * preStride + cix + 1];
            }
            float s0 = par ? z0 : z2;
            float s1 = par ? z1 : z3;
            float q0 = __shfl_xor_sync(0xffffffffu, s0, 1);
            float q1 = __shfl_xor_sync(0xffffffffu, s1, 1);
            float zi = par ? q0 : z0;
            float zf = par ? q1 : z1;
            float zg = par ? z2 : q0;
            float zo = par ? z3 : q1;
            const int j = cix >> 2;
            const size_t si = (size_t)r * NH + j;
            float ig = sigf(zi), fg = sigf(zf), og = sigf(zo);
            float gg = tanhff(zg);
            float cn = fg * cState[si] + ig * gg;
            float h = og * tanhff(cn);
            cState[si] = cn;
            __half hh = __float2half(h);
            hOut[si] = hh;
            if (yOut) yOut[(size_t)r * yStride + j] = hh;
            if (yF32) yF32[(size_t)r * yStride + j] = h;
        }
    }
}

// ---------------- final dense ----------------
__global__ void k_dense(const float* __restrict__ w, const float* __restrict__ b,
                        float* __restrict__ out) {
    int r = blockIdx.x * 8 + (threadIdx.x >> 5);
    int lane = threadIdx.x & 31;
    const float* row = g_D1 + (size_t)r * NH;
    float s = 0.0f;
#pragma unroll
    for (int k = lane; k < NH; k += 32) s += row[k] * w[k];
#pragma unroll
    for (int o = 16; o; o >>= 1) s += __shfl_xor_sync(0xffffffffu, s, o);
    if (lane == 0) out[r] = s + b[0];
}

// ---------------- host ----------------
extern "C" void kernel_launch(void* const* d_in, const int* in_sizes, int n_in,
                              void* d_out, int out_size) {
    (void)in_sizes; (void)n_in; (void)out_size;
    const float* x      = (const float*)d_in[0];
    const float* eW0    = (const float*)d_in[2];
    const float* eU0    = (const float*)d_in[3];
    const float* eb0    = (const float*)d_in[4];
    const float* eW1    = (const float*)d_in[5];
    const float* eU1    = (const float*)d_in[6];
    const float* eb1    = (const float*)d_in[7];
    const float* dU0    = (const float*)d_in[9];
    const float* db0    = (const float*)d_in[10];
    const float* dW1    = (const float*)d_in[11];
    const float* dU1    = (const float*)d_in[12];
    const float* db1    = (const float*)d_in[13];
    const float* denseW = (const float*)d_in[14];
    const float* denseb = (const float*)d_in[15];

    cudaFuncSetAttribute(k_gemm1<true>,  cudaFuncAttributeMaxDynamicSharedMemorySize, SMEM_DYN);
    cudaFuncSetAttribute(k_gemm1<false>, cudaFuncAttributeMaxDynamicSharedMemorySize, SMEM_DYN);

    void *pZ, *pX, *pY, *pD1, *pA, *pB, *pCA, *pCB, *pW, *pBs;
    cudaGetSymbolAddress(&pZ, g_Z);
    cudaGetSymbolAddress(&pX, g_X);
    cudaGetSymbolAddress(&pY, g_Y);
    cudaGetSymbolAddress(&pD1, g_D1);
    cudaGetSymbolAddress(&pA, g_hA);
    cudaGetSymbolAddress(&pB, g_hB);
    cudaGetSymbolAddress(&pCA, g_cA);  cudaGetSymbolAddress(&pCB, g_cB);
    cudaGetSymbolAddress(&pW, g_WT);
    cudaGetSymbolAddress(&pBs, g_bias);

    float* Z = (float*)pZ;
    __half* X = (__half*)pX;
    __half* Y = (__half*)pY;
    float* D1 = (float*)pD1;
    __half* hA[2] = {(__half*)pA, (__half*)pA + NB * NH};
    __half* hB[2] = {(__half*)pB, (__half*)pB + NB * NH};
    float* cA = (float*)pCA; float* cB = (float*)pCB;
    __half* W = (__half*)pW;
    float* Bias = (float*)pBs;

    // --- prep: 2 launches ---
    {
        long long wtot = 2048LL * 128 + 6LL * 2048 * 512;
        k_prep_weights<<<(int)((wtot + 255) / 256), 256>>>(eW0, eU0, eW1, eU1, dU0, dW1, dU1);
        long long mtot = 4LL * NG + (long long)NB * NT * 128 + (long long)NB * NH;
        k_prep_misc<<<(int)((mtot + 255) / 256), 256>>>(x, eb0, eb1, db0, db1);
    }

    const dim3 blk(256);
    const dim3 gStep(NB / 32, 16);   // 512 CTAs

    // --- encoder L0: precompute x@eW0, then 64 recurrent steps ---
    k_gemm1<false><<<dim3(NB * NT / 32, 16), blk, SMEM_DYN>>>(
        X, 128, W + O_eW0, 128, 2, Z,
        nullptr, 0, nullptr, nullptr, nullptr, nullptr, 0, nullptr);
    for (int t = 0; t < NT; t++) {
        k_gemm1<true><<<gStep, blk, SMEM_DYN>>>(
            hA[t & 1], NH, W + O_eU0, NH, 8, nullptr,
            Z + (size_t)t * NG, (long long)NT * NG, Bias + 0 * NG, cA,
            hA[(t + 1) & 1],
            Y + (size_t)t * NH, (long long)NT * NH, nullptr);
    }
    // --- encoder L1: precompute y0@eW1, then 64 steps ---
    k_gemm1<false><<<dim3(NB * NT / 32, 16), blk, SMEM_DYN>>>(
        Y, NH, W + O_eW1, NH, 8, Z,
        nullptr, 0, nullptr, nullptr, nullptr, nullptr, 0, nullptr);
    for (int t = 0; t < NT; t++) {
        k_gemm1<true><<<gStep, blk, SMEM_DYN>>>(
            hB[t & 1], NH, W + O_eU1, NH, 8, nullptr,
            Z + (size_t)t * NG, (long long)NT * NG, Bias + 1 * NG, cB,
            hB[(t + 1) & 1],
            nullptr, 0, nullptr);
    }
    // --- decoder L0: zero input; continues from enc-L0 final state ---
    for (int t = 0; t < NSEG; t++) {
        k_gemm1<true><<<gStep, blk, SMEM_DYN>>>(
            hA[t & 1], NH, W + O_dU0, NH, 8, nullptr,
            nullptr, 0, Bias + 2 * NG, cA,
            hA[(t + 1) & 1],
            Y + (size_t)t * NH, (long long)NSEG * NH, nullptr);
    }
    // --- decoder L1: precompute d0@dW1, then 32 steps, emit fp32 d1 ---
    k_gemm1<false><<<dim3(NB * NSEG / 32, 16), blk, SMEM_DYN>>>(
        Y, NH, W + O_dW1, NH, 8, Z,
        nullptr, 0, nullptr, nullptr, nullptr, nullptr, 0, nullptr);
    for (int t = 0; t < NSEG; t++) {
        k_gemm1<true><<<gStep, blk, SMEM_DYN>>>(
            hB[t & 1], NH, W + O_dU1, NH, 8, nullptr,
            Z + (size_t)t * NG, (long long)NSEG * NG, Bias + 3 * NG, cB,
            hB[(t + 1) & 1],
            nullptr, (long long)NSEG * NH, D1 + (size_t)t * NH);
    }
    // --- final dense ---
    k_dense<<<NB * NSEG / 8, 256>>>(denseW, denseb, (float*)d_out);
}

// round 13
// speedup vs baseline: 1.5250x; 1.1180x over previous
#include <cuda_runtime.h>
#include <cuda_fp16.h>
#include <cstdint>
#include <cstddef>

#define NB 1024
#define NT 64
#define NF 121
#define NH 512
#define NSEG 32
#define NG 2048   // 4*H

// ---------------- scratch (device globals; no allocation) ----------------
__device__ __align__(16) float   g_Z   [(size_t)NB * NT * NG];    // precomputed z (interleaved cols)
__device__ __align__(16) __half  g_X   [(size_t)NB * NT * 128];   // x fp16, K padded 121->128
__device__ __align__(16) __half  g_Y   [(size_t)NB * NT * NH];    // y0 / d0 staging (fp16)
__device__ __align__(16) float   g_D1  [(size_t)NB * NSEG * NH];  // decoder L1 outputs
__device__ __align__(16) __half  g_hA  [2][NB * NH];              // ping-pong h (enc0->dec0)
__device__ __align__(16) __half  g_hB  [2][NB * NH];              // (enc1->dec1)
__device__ __align__(16) float   g_cA  [NB * NH];
__device__ __align__(16) float   g_cB  [NB * NH];
// weight arena: W^T fp16, rows = interleaved out-col (j*4+gate), K contiguous.
#define O_eW0 0
#define O_eU0 (2048*128)
#define O_eW1 (O_eU0 + 2048*512)
#define O_eU1 (O_eW1 + 2048*512)
#define O_dU0 (O_eU1 + 2048*512)
#define O_dW1 (O_dU0 + 2048*512)
#define O_dU1 (O_dW1 + 2048*512)
#define W_TOTAL (O_dU1 + 2048*512)
__device__ __align__(16) __half  g_WT  [W_TOTAL];
__device__ __align__(16) float   g_bias[4 * NG];   // eb0,eb1,db0,db1 (interleaved)

// ---------------- helpers ----------------
__device__ __forceinline__ float rcpa(float x) {
    float r; asm("rcp.approx.f32 %0, %1;" : "=f"(r) : "f"(x)); return r;
}
__device__ __forceinline__ float sigf(float x)  { return rcpa(1.0f + __expf(-x)); }
__device__ __forceinline__ float tanhff(float x){ return __fmaf_rn(2.0f, rcpa(1.0f + __expf(-2.0f * x)), -1.0f); }

__device__ __forceinline__ uint32_t smem_u32(const void* p) {
    uint32_t a;
    asm("{ .reg .u64 t; cvta.to.shared.u64 t, %1; cvt.u32.u64 %0, t; }" : "=r"(a) : "l"(p));
    return a;
}
__device__ __forceinline__ void mma16816h(float* d, const unsigned* a, unsigned b0, unsigned b1) {
    asm volatile(
        "mma.sync.aligned.m16n8k16.row.col.f32.f16.f16.f32 "
        "{%0,%1,%2,%3}, {%4,%5,%6,%7}, {%8,%9}, {%0,%1,%2,%3};"
        : "+f"(d[0]), "+f"(d[1]), "+f"(d[2]), "+f"(d[3])
        : "r"(a[0]), "r"(a[1]), "r"(a[2]), "r"(a[3]), "r"(b0), "r"(b1));
}
__device__ __forceinline__ void ldsm4(uint32_t* r, uint32_t addr) {
    asm volatile("ldmatrix.sync.aligned.m8n8.x4.shared.b16 {%0,%1,%2,%3}, [%4];"
                 : "=r"(r[0]), "=r"(r[1]), "=r"(r[2]), "=r"(r[3]) : "r"(addr));
}
__device__ __forceinline__ void cpa16(uint32_t dst, const void* src) {
    asm volatile("cp.async.cg.shared.global [%0], [%1], 16;" :: "r"(dst), "l"(src));
}
#define CP_COMMIT() asm volatile("cp.async.commit_group;" ::: "memory")

// smem: two 20KB stages: A 4K | B 16K  (40KB total -> 4 CTAs/SM)
#define BUF_STRIDE 20480u
#define SMEM_DYN   (2 * 20480)

// ---------------- merged prep kernels ----------------
__global__ void k_prep_weights(const float* __restrict__ eW0, const float* __restrict__ eU0,
                               const float* __restrict__ eW1, const float* __restrict__ eU1,
                               const float* __restrict__ dU0, const float* __restrict__ dW1,
                               const float* __restrict__ dU1) {
    long long idx = (long long)blockIdx.x * blockDim.x + threadIdx.x;
    const float* src; int K, Kpad; size_t off;
    const long long S0 = 2048LL * 128, S = 2048LL * 512;
    if (idx < S0)               { src = eW0; K = NF;  Kpad = 128; off = O_eW0; }
    else if ((idx -= S0) < S)   { src = eU0; K = NH;  Kpad = 512; off = O_eU0; }
    else if ((idx -= S) < S)    { src = eW1; K = NH;  Kpad = 512; off = O_eW1; }
    else if ((idx -= S) < S)    { src = eU1; K = NH;  Kpad = 512; off = O_eU1; }
    else if ((idx -= S) < S)    { src = dU0; K = NH;  Kpad = 512; off = O_dU0; }
    else if ((idx -= S) < S)    { src = dW1; K = NH;  Kpad = 512; off = O_dW1; }
    else if ((idx -= S) < S)    { src = dU1; K = NH;  Kpad = 512; off = O_dU1; }
    else return;
    int n = (int)(idx / Kpad), k = (int)(idx % Kpad);
    float v = (k < K) ? src[(size_t)k * NG + n] : 0.0f;
    int cil = (n & 511) * 4 + (n >> 9);
    g_WT[off + (size_t)cil * Kpad + k] = __float2half(v);
}

__global__ void k_prep_misc(const float* __restrict__ x,
                            const float* __restrict__ eb0, const float* __restrict__ eb1,
                            const float* __restrict__ db0, const float* __restrict__ db1) {
    long long idx = (long long)blockIdx.x * blockDim.x + threadIdx.x;
    if (idx < 4 * NG) {
        int which = (int)(idx >> 11), n = (int)(idx & 2047);
        const float* b = (which == 0) ? eb0 : (which == 1) ? eb1 : (which == 2) ? db0 : db1;
        g_bias[which * NG + (n & 511) * 4 + (n >> 9)] = b[n];
        return;
    }
    idx -= 4 * NG;
    if (idx < (long long)NB * NT * 128) {
        int r = (int)(idx >> 7), k = (int)(idx & 127);
        g_X[idx] = __float2half((k < NF) ? x[(size_t)r * NF + k] : 0.0f);
        return;
    }
    idx -= (long long)NB * NT * 128;
    if (idx < NB * NH) {
        __half z = __float2half(0.0f);
        g_hA[0][idx] = z; g_hB[0][idx] = z;
        g_cA[idx] = 0.0f; g_cB[idx] = 0.0f;
    }
}

// ---------------- fp16 GEMM: small CTAs, 4 CTAs/SM, 2-stage cp.async ----------------
// C[M][2048] = A[M][K] @ B^T ; A fp16, B stored [n][k] K-contig fp16.
// Tile BM=32 x BN=128; 8 warps (2x4), warp tile 16x32. K chunks of 64, 2 smem stages.
template <bool LSTM>
__global__ __launch_bounds__(256, 4)
void k_gemm1(const __half* __restrict__ A, int lda,
             const __half* __restrict__ B, int ldw,
             int nc,
             float* __restrict__ outZ,
             const float* __restrict__ pre, long long preStride,
             const float* __restrict__ bias,
             float* __restrict__ cState,
             __half* __restrict__ hOut,
             __half* __restrict__ yOut, long long yStride,
             float* __restrict__ yF32) {
    extern __shared__ __align__(128) char smem[];
    const uint32_t sb = smem_u32(smem);
    const int tid = threadIdx.x, lane = tid & 31, warp = tid >> 5;
    const int wm = warp >> 2;          // 0..1  (16 M-rows each)
    const int wn = warp & 3;           // 0..3  (32 N-cols each)
    const int bm = blockIdx.x * 32;
    const int bn = blockIdx.y * 128;

    float acc[4][4];
#pragma unroll
    for (int b = 0; b < 4; b++)
#pragma unroll
        for (int c = 0; c < 4; c++) acc[b][c] = 0.0f;

    const uint32_t a_lc = (uint32_t)(lane & 16);            // ldmatrix col sel
    const uint32_t b_lc = (uint32_t)((lane & 8) << 1);
    const int b_r8 = (lane & 16) >> 1;

    auto issue = [&](int c) {
        const int kb = c * 64;
        const uint32_t dbase = sb + (uint32_t)(c & 1) * BUF_STRIDE;
        {   // A: 32 rows x 128B = 256 x 16B, one per thread
            int row = tid >> 3, seg = tid & 7;
            uint32_t off = (uint32_t)(row * 128) + (uint32_t)((seg * 16) ^ ((row & 7) * 16));
            cpa16(dbase + off, A + (size_t)(bm + row) * lda + kb + seg * 8);
        }
        {   // B: 128 rows x 128B = 1024 x 16B, four per thread
            const uint32_t db = dbase + 4096u;
#pragma unroll
            for (int it = 0; it < 4; it++) {
                int u = it * 256 + tid;
                int row = u >> 3, seg = u & 7;
                uint32_t off = (uint32_t)(row * 128) + (uint32_t)((seg * 16) ^ ((row & 7) * 16));
                cpa16(db + off, B + (size_t)(bn + row) * ldw + kb + seg * 8);
            }
        }
        CP_COMMIT();
    };

    issue(0);
    for (int c = 0; c < nc; ++c) {
        asm volatile("cp.async.wait_group 0;" ::: "memory");   // chunk c arrived
        __syncthreads();   // all warps see chunk c; all warps are past chunk c-1's reads
        if (c + 1 < nc) issue(c + 1);   // stage (c+1)&1 was last read in chunk c-1 -> safe
        const uint32_t dbase = sb + (uint32_t)(c & 1) * BUF_STRIDE;
#pragma unroll
        for (int k16 = 0; k16 < 4; ++k16) {
            const uint32_t kcol = (uint32_t)(k16 * 32);
            uint32_t af[4];
            {
                int r = wm * 16 + (lane & 15);
                uint32_t addr = dbase + (uint32_t)(r * 128)
                              + ((kcol + a_lc) ^ (uint32_t)((r & 7) * 16));
                ldsm4(af, addr);
            }
            uint32_t bfr[4][2];
#pragma unroll
            for (int jq = 0; jq < 2; ++jq) {
                int r = wn * 32 + jq * 16 + (lane & 7) + b_r8;
                uint32_t addr = dbase + 4096u + (uint32_t)(r * 128)
                              + ((kcol + b_lc) ^ (uint32_t)((r & 7) * 16));
                uint32_t t4[4];
                ldsm4(t4, addr);
                bfr[jq * 2][0] = t4[0];     bfr[jq * 2][1] = t4[1];
                bfr[jq * 2 + 1][0] = t4[2]; bfr[jq * 2 + 1][1] = t4[3];
            }
#pragma unroll
            for (int jt = 0; jt < 4; ++jt)
                mma16816h(acc[jt], af, bfr[jt][0], bfr[jt][1]);
        }
    }

    // ---------------- epilogue ----------------
    if (!LSTM) {
        int r = bm + wm * 16 + (lane >> 2);
#pragma unroll
        for (int jt = 0; jt < 4; jt++) {
            int cix = bn + wn * 32 + jt * 8 + (lane & 3) * 2;
            float* o = outZ + (size_t)r * NG + cix;
            o[0] = acc[jt][0]; o[1] = acc[jt][1];
            o += (size_t)8 * NG;
            o[0] = acc[jt][2]; o[1] = acc[jt][3];
        }
    } else {
        // all-lane LSTM epilogue: even lane -> row rA, odd lane -> rA+8.
        const int par = lane & 1;
        const int rA = bm + wm * 16 + (lane >> 2);
        const int r  = rA + par * 8;
#pragma unroll
        for (int jt = 0; jt < 4; jt++) {
            const int cix = bn + wn * 32 + jt * 8 + (lane & 3) * 2;
            float z0 = acc[jt][0] + bias[cix];
            float z1 = acc[jt][1] + bias[cix + 1];
            float z2 = acc[jt][2] + bias[cix];
            float z3 = acc[jt][3] + bias[cix + 1];
            if (pre) {
                z0 += pre[(size_t)rA * preStride + cix];
                z1 += pre[(size_t)rA * preStride + cix + 1];
                z2 += pre[(size_t)(rA + 8) * preStride + cix];
                z3 += pre[(size_t)(rA + 8) * preStride + cix + 1];
            }
            float s0 = par ? z0 : z2;
            float s1 = par ? z1 : z3;
            float q0 = __shfl_xor_sync(0xffffffffu, s0, 1);
            float q1 = __shfl_xor_sync(0xffffffffu, s1, 1);
            float zi = par ? q0 : z0;
            float zf = par ? q1 : z1;
            float zg = par ? z2 : q0;
            float zo = par ? z3 : q1;
            const int j = cix >> 2;
            const size_t si = (size_t)r * NH + j;
            float ig = sigf(zi), fg = sigf(zf), og = sigf(zo);
            float gg = tanhff(zg);
            float cn = fg * cState[si] + ig * gg;
            float h = og * tanhff(cn);
            cState[si] = cn;
            __half hh = __float2half(h);
            hOut[si] = hh;
            if (yOut) yOut[(size_t)r * yStride + j] = hh;
            if (yF32) yF32[(size_t)r * yStride + j] = h;
        }
    }
}

// ---------------- final dense ----------------
__global__ void k_dense(const float* __restrict__ w, const float* __restrict__ b,
                        float* __restrict__ out) {
    int r = blockIdx.x * 8 + (threadIdx.x >> 5);
    int lane = threadIdx.x & 31;
    const float* row = g_D1 + (size_t)r * NH;
    float s = 0.0f;
#pragma unroll
    for (int k = lane; k < NH; k += 32) s += row[k] * w[k];
#pragma unroll
    for (int o = 16; o; o >>= 1) s += __shfl_xor_sync(0xffffffffu, s, o);
    if (lane == 0) out[r] = s + b[0];
}

// ---------------- host ----------------
extern "C" void kernel_launch(void* const* d_in, const int* in_sizes, int n_in,
                              void* d_out, int out_size) {
    (void)in_sizes; (void)n_in; (void)out_size;
    const float* x      = (const float*)d_in[0];
    const float* eW0    = (const float*)d_in[2];
    const float* eU0    = (const float*)d_in[3];
    const float* eb0    = (const float*)d_in[4];
    const float* eW1    = (const float*)d_in[5];
    const float* eU1    = (const float*)d_in[6];
    const float* eb1    = (const float*)d_in[7];
    const float* dU0    = (const float*)d_in[9];
    const float* db0    = (const float*)d_in[10];
    const float* dW1    = (const float*)d_in[11];
    const float* dU1    = (const float*)d_in[12];
    const float* db1    = (const float*)d_in[13];
    const float* denseW = (const float*)d_in[14];
    const float* denseb = (const float*)d_in[15];

    cudaFuncSetAttribute(k_gemm1<true>,  cudaFuncAttributeMaxDynamicSharedMemorySize, SMEM_DYN);
    cudaFuncSetAttribute(k_gemm1<false>, cudaFuncAttributeMaxDynamicSharedMemorySize, SMEM_DYN);

    void *pZ, *pX, *pY, *pD1, *pA, *pB, *pCA, *pCB, *pW, *pBs;
    cudaGetSymbolAddress(&pZ, g_Z);
    cudaGetSymbolAddress(&pX, g_X);
    cudaGetSymbolAddress(&pY, g_Y);
    cudaGetSymbolAddress(&pD1, g_D1);
    cudaGetSymbolAddress(&pA, g_hA);
    cudaGetSymbolAddress(&pB, g_hB);
    cudaGetSymbolAddress(&pCA, g_cA);  cudaGetSymbolAddress(&pCB, g_cB);
    cudaGetSymbolAddress(&pW, g_WT);
    cudaGetSymbolAddress(&pBs, g_bias);

    float* Z = (float*)pZ;
    __half* X = (__half*)pX;
    __half* Y = (__half*)pY;
    float* D1 = (float*)pD1;
    __half* hA[2] = {(__half*)pA, (__half*)pA + NB * NH};
    __half* hB[2] = {(__half*)pB, (__half*)pB + NB * NH};
    float* cA = (float*)pCA; float* cB = (float*)pCB;
    __half* W = (__half*)pW;
    float* Bias = (float*)pBs;

    // --- prep: 2 launches ---
    {
        long long wtot = 2048LL * 128 + 6LL * 2048 * 512;
        k_prep_weights<<<(int)((wtot + 255) / 256), 256>>>(eW0, eU0, eW1, eU1, dU0, dW1, dU1);
        long long mtot = 4LL * NG + (long long)NB * NT * 128 + (long long)NB * NH;
        k_prep_misc<<<(int)((mtot + 255) / 256), 256>>>(x, eb0, eb1, db0, db1);
    }

    const dim3 blk(256);
    const dim3 gStep(NB / 32, 16);   // 512 CTAs -> fully resident at 4 CTAs/SM

    // --- encoder L0: precompute x@eW0, then 64 recurrent steps ---
    k_gemm1<false><<<dim3(NB * NT / 32, 16), blk, SMEM_DYN>>>(
        X, 128, W + O_eW0, 128, 2, Z,
        nullptr, 0, nullptr, nullptr, nullptr, nullptr, 0, nullptr);
    for (int t = 0; t < NT; t++) {
        k_gemm1<true><<<gStep, blk, SMEM_DYN>>>(
            hA[t & 1], NH, W + O_eU0, NH, 8, nullptr,
            Z + (size_t)t * NG, (long long)NT * NG, Bias + 0 * NG, cA,
            hA[(t + 1) & 1],
            Y + (size_t)t * NH, (long long)NT * NH, nullptr);
    }
    // --- encoder L1: precompute y0@eW1, then 64 steps ---
    k_gemm1<false><<<dim3(NB * NT / 32, 16), blk, SMEM_DYN>>>(
        Y, NH, W + O_eW1, NH, 8, Z,
        nullptr, 0, nullptr, nullptr, nullptr, nullptr, 0, nullptr);
    for (int t = 0; t < NT; t++) {
        k_gemm1<true><<<gStep, blk, SMEM_DYN>>>(
            hB[t & 1], NH, W + O_eU1, NH, 8, nullptr,
            Z + (size_t)t * NG, (long long)NT * NG, Bias + 1 * NG, cB,
            hB[(t + 1) & 1],
            nullptr, 0, nullptr);
    }
    // --- decoder L0: zero input; continues from enc-L0 final state ---
    for (int t = 0; t < NSEG; t++) {
        k_gemm1<true><<<gStep, blk, SMEM_DYN>>>(
            hA[t & 1], NH, W + O_dU0, NH, 8, nullptr,
            nullptr, 0, Bias + 2 * NG, cA,
            hA[(t + 1) & 1],
            Y + (size_t)t * NH, (long long)NSEG * NH, nullptr);
    }
    // --- decoder L1: precompute d0@dW1, then 32 steps, emit fp32 d1 ---
    k_gemm1<false><<<dim3(NB * NSEG / 32, 16), blk, SMEM_DYN>>>(
        Y, NH, W + O_dW1, NH, 8, Z,
        nullptr, 0, nullptr, nullptr, nullptr, nullptr, 0, nullptr);
    for (int t = 0; t < NSEG; t++) {
        k_gemm1<true><<<gStep, blk, SMEM_DYN>>>(
            hB[t & 1], NH, W + O_dU1, NH, 8, nullptr,
            Z + (size_t)t * NG, (long long)NSEG * NG, Bias + 3 * NG, cB,
            hB[(t + 1) & 1],
            nullptr, (long long)NSEG * NH, D1 + (size_t)t * NH);
    }
    // --- final dense ---
    k_dense<<<NB * NSEG / 8, 256>>>(denseW, denseb, (float*)d_out);
}